// round 9
// baseline (speedup 1.0000x reference)
#include <cuda_runtime.h>
#include <cuda_fp16.h>
#include <math.h>
#include <stdint.h>

#define MR 2
#define NE 8
#define CD 1024
#define DD 256
#define BB 32
#define SS 512

// down stage: A(x) 8KB | B(dwT, 256 rows) 16KB = 24KB; 3 stages = 72KB
#define DSTAGE 24576
#define DOFF_B 8192
// up stage: B(uwT) two 8KB k32 sub-blocks = 16KB; 3 stages = 48KB (reuses region)
#define USTAGE 16384
// z tile in smem: 128 x 256 fp16 = 64KB, as 8 regions of [128 rows x 32 d] 8KB
#define Z_OFF  73728
#define SMEM_TOTAL (Z_OFF + 65536)   // 139264 -> 1 CTA/SM

typedef __half fp16;

// ---------------- static device scratch (no allocs) ----------------
__device__ fp16 g_x[(size_t)BB * SS * CD];        // x fp16, C contiguous
__device__ fp16 g_dwT[(size_t)MR * NE * DD * CD]; // [D][C]
__device__ fp16 g_uwT[(size_t)MR * NE * CD * DD]; // [C][D]

// ---------------- ptx helpers ----------------
__device__ __forceinline__ uint32_t smem_u32(const void* p) {
    uint32_t a;
    asm("{ .reg .u64 t; cvta.to.shared.u64 t, %1; cvt.u32.u64 %0, t; }" : "=r"(a) : "l"(p));
    return a;
}
#define CP16(dst, src) \
    asm volatile("cp.async.cg.shared.global [%0], [%1], 16;" :: "r"(dst), "l"(src))
#define CP_COMMIT() asm volatile("cp.async.commit_group;")
#define CP_WAIT1()  asm volatile("cp.async.wait_group 1;")
#define CP_WAIT0()  asm volatile("cp.async.wait_group 0;")

#define LDSM4(r, a) \
    asm volatile("ldmatrix.sync.aligned.m8n8.x4.shared.b16 {%0,%1,%2,%3}, [%4];" \
        : "=r"((r)[0]), "=r"((r)[1]), "=r"((r)[2]), "=r"((r)[3]) : "r"(a))

#define MMA(d, a, b0, b1) \
    asm volatile("mma.sync.aligned.m16n8k16.row.col.f32.f16.f16.f32 " \
        "{%0,%1,%2,%3},{%4,%5,%6,%7},{%8,%9},{%0,%1,%2,%3};" \
        : "+f"((d)[0]), "+f"((d)[1]), "+f"((d)[2]), "+f"((d)[3]) \
        : "r"((a)[0]), "r"((a)[1]), "r"((a)[2]), "r"((a)[3]), "r"(b0), "r"(b1))

// XOR swizzle for 64B rows (4 x 16B chunks); conflict-free ldmatrix
__device__ __forceinline__ uint32_t swz(uint32_t row, uint32_t chunk) {
    return row * 64u + ((chunk ^ ((row >> 1) & 3u)) << 4);
}

// ---------------- fused kernel: z = silu(x@dw+db) in smem, then out = z@uw ----
__global__ void __launch_bounds__(512, 1)
fused_mma(const int* __restrict__ eidx, const float* __restrict__ db,
          float* __restrict__ out) {
    extern __shared__ char smem[];
    const uint32_t smem_b = smem_u32(smem);
    const int tid = threadIdx.x, lane = tid & 31, warp = tid >> 5;
    const int stile = blockIdx.x, b = blockIdx.y, m = blockIdx.z;
    const int e = eidx[m * BB + b];
    const int r15 = lane & 15, chi = lane >> 4;
    const int r0 = lane >> 2, cp = 2 * (lane & 3);

    const fp16* A1 = g_x   + ((size_t)b * SS + stile * 128) * CD;
    const fp16* B1 = g_dwT + (size_t)(m * NE + e) * DD * CD;      // full 256 D rows
    const fp16* B2 = g_uwT + (size_t)(m * NE + e) * CD * DD;

    // ================= phase 1: down =================
    {
        const int wm = (warp & 1) * 64, wn = (warp >> 1) * 32;    // 2m x 8n warps
        const uint32_t a0 = swz((uint32_t)(wm + r15), (uint32_t)chi);
        const uint32_t b0 = swz((uint32_t)(wn + r15), (uint32_t)chi) + DOFF_B;

        // stage loader: 3x CP16/thread (A 512 chunks, B 1024 chunks)
        const int ar = tid >> 2, ac = tid & 3;
        const uint32_t a_so = swz(ar, ac);
        const size_t a_go = (size_t)ar * CD + ac * 8;
        uint32_t b_so[2]; size_t b_go[2];
        #pragma unroll
        for (int i = 0; i < 2; i++) {
            int q = tid + (i << 9);
            int rb = q >> 2, cb = q & 3;
            b_so[i] = DOFF_B + swz(rb, cb);
            b_go[i] = (size_t)rb * CD + cb * 8;
        }
        #define DLOAD(sbase, kc) do { \
            CP16((sbase) + a_so, A1 + a_go + (kc)); \
            CP16((sbase) + b_so[0], B1 + b_go[0] + (kc)); \
            CP16((sbase) + b_so[1], B1 + b_go[1] + (kc)); \
        } while (0)

        DLOAD(smem_b, 0);           CP_COMMIT();
        DLOAD(smem_b + DSTAGE, 32); CP_COMMIT();

        float acc[4][4][4];
        #pragma unroll
        for (int i = 0; i < 4; i++)
            #pragma unroll
            for (int j = 0; j < 4; j++)
                #pragma unroll
                for (int q = 0; q < 4; q++) acc[i][j][q] = 0.f;

        int rs = 0, ps = 2;   // ring indices: current stage, prefetch stage
        for (int k = 0; k < 32; k++) {
            if (k + 2 < 32) { CP_WAIT1(); } else { CP_WAIT0(); }
            __syncthreads();
            if (k + 2 < 32) {
                DLOAD(smem_b + ps * DSTAGE, (k + 2) * 32);
                CP_COMMIT();
                ps = (ps == 2) ? 0 : ps + 1;
            }
            const uint32_t stg = smem_b + rs * DSTAGE;
            rs = (rs == 2) ? 0 : rs + 1;

            uint32_t ah[4][4], bb[2][4];
            #pragma unroll
            for (int ks = 0; ks < 2; ks++) {
                const uint32_t ax = stg + (ks ? (a0 ^ 32u) : a0);
                const uint32_t bx = stg + (ks ? (b0 ^ 32u) : b0);
                LDSM4(bb[0], bx);
                LDSM4(bb[1], bx + 1024);
                LDSM4(ah[0], ax);
                LDSM4(ah[1], ax + 1024);
                LDSM4(ah[2], ax + 2048);
                LDSM4(ah[3], ax + 3072);
                #pragma unroll
                for (int mt = 0; mt < 4; mt++)
                    #pragma unroll
                    for (int nt = 0; nt < 4; nt++)
                        MMA(acc[mt][nt], ah[mt], bb[nt >> 1][nt & 1], bb[nt >> 1][2 + (nt & 1)]);
            }
        }

        // epilogue: bias + silu -> z in smem (region = wn>>5, swizzled rows)
        const float* bias = db + (size_t)(m * NE + e) * DD;
        char* zreg = smem + Z_OFF + (wn >> 5) * 8192;
        #pragma unroll
        for (int mt = 0; mt < 4; mt++) {
            #pragma unroll
            for (int nt = 0; nt < 4; nt++) {
                const float2 bv = *reinterpret_cast<const float2*>(bias + wn + nt * 8 + cp);
                #pragma unroll
                for (int h = 0; h < 2; h++) {
                    float v0 = acc[mt][nt][2 * h + 0] + bv.x;
                    float v1 = acc[mt][nt][2 * h + 1] + bv.y;
                    v0 = v0 / (1.f + __expf(-v0));
                    v1 = v1 / (1.f + __expf(-v1));
                    __half2 hp; hp.x = __float2half(v0); hp.y = __float2half(v1);
                    const uint32_t row = wm + mt * 16 + r0 + h * 8;
                    *reinterpret_cast<__half2*>(zreg + swz(row, nt) + cp * 2) = hp;
                }
            }
        }
    }
    __syncthreads();   // z complete + all down staging reads done

    // ================= phase 2: up (A = z from smem) =================
    {
        const int um = (warp & 3) * 32, un = (warp >> 2) * 32;    // 4m x 4n warps
        const uint32_t au0 = swz((uint32_t)(um + r15), (uint32_t)chi);
        const uint32_t bu0 = swz((uint32_t)(un + r15), (uint32_t)chi);

        // up stage loader: 2x CP16/thread; iter t: ct = t>>2, kk = t&3 (K64)
        const int br = tid >> 2, bc = tid & 3;
        const uint32_t u_so = swz(br, bc);
        #define ULOAD(t, sbase) do { \
            const fp16* src = B2 + (size_t)(((t) >> 2) * 128 + br) * DD + ((t) & 3) * 64 + bc * 8; \
            CP16((sbase) + u_so, src); \
            CP16((sbase) + 8192 + u_so, src + 32); \
        } while (0)

        ULOAD(0, smem_b);          CP_COMMIT();
        ULOAD(1, smem_b + USTAGE); CP_COMMIT();

        float acc[2][4][4];
        #pragma unroll
        for (int i = 0; i < 2; i++)
            #pragma unroll
            for (int j = 0; j < 4; j++)
                #pragma unroll
                for (int q = 0; q < 4; q++) acc[i][j][q] = 0.f;

        const size_t orow0 = ((size_t)(m * BB + b) * SS + stile * 128);
        int rs = 0, ps = 2;
        for (int t = 0; t < 32; t++) {
            if (t + 2 < 32) { CP_WAIT1(); } else { CP_WAIT0(); }
            __syncthreads();
            if (t + 2 < 32) {
                ULOAD(t + 2, smem_b + ps * USTAGE);
                CP_COMMIT();
                ps = (ps == 2) ? 0 : ps + 1;
            }
            const uint32_t stg = smem_b + rs * USTAGE;
            rs = (rs == 2) ? 0 : rs + 1;
            const int kk = t & 3;

            uint32_t ua[2][4], ub[2][4];
            #pragma unroll
            for (int q = 0; q < 2; q++) {
                const uint32_t zr = smem_b + Z_OFF + (uint32_t)(kk * 2 + q) * 8192;
                const uint32_t bregion = stg + q * 8192;
                #pragma unroll
                for (int ks = 0; ks < 2; ks++) {
                    const uint32_t ax = zr + (ks ? (au0 ^ 32u) : au0);
                    const uint32_t bx = bregion + (ks ? (bu0 ^ 32u) : bu0);
                    LDSM4(ub[0], bx);
                    LDSM4(ub[1], bx + 1024);
                    LDSM4(ua[0], ax);
                    LDSM4(ua[1], ax + 1024);
                    #pragma unroll
                    for (int mt = 0; mt < 2; mt++)
                        #pragma unroll
                        for (int nt = 0; nt < 4; nt++)
                            MMA(acc[mt][nt], ua[mt], ub[nt >> 1][nt & 1], ub[nt >> 1][2 + (nt & 1)]);
                }
            }

            if (kk == 3) {    // ctile done: write out, reset acc
                const int ct = t >> 2;
                #pragma unroll
                for (int mt = 0; mt < 2; mt++)
                    #pragma unroll
                    for (int nt = 0; nt < 4; nt++) {
                        const int col = ct * 128 + un + nt * 8 + cp;
                        #pragma unroll
                        for (int h = 0; h < 2; h++) {
                            const size_t off = (orow0 + um + mt * 16 + r0 + h * 8) * CD + col;
                            *reinterpret_cast<float2*>(out + off) =
                                make_float2(acc[mt][nt][2 * h + 0], acc[mt][nt][2 * h + 1]);
                            acc[mt][nt][2 * h + 0] = 0.f;
                            acc[mt][nt][2 * h + 1] = 0.f;
                        }
                    }
            }
        }
    }
}

// ---------------- prep: x fp32 -> fp16 ----------------------------------------
__global__ void __launch_bounds__(256)
x_cvt(const float* __restrict__ x) {
    size_t i = ((size_t)blockIdx.x * 256 + threadIdx.x) * 4;
    float4 v = *reinterpret_cast<const float4*>(x + i);
    __half2 p0, p1;
    p0.x = __float2half(v.x); p0.y = __float2half(v.y);
    p1.x = __float2half(v.z); p1.y = __float2half(v.w);
    *reinterpret_cast<uint2*>(g_x + i) =
        make_uint2(*reinterpret_cast<uint32_t*>(&p0), *reinterpret_cast<uint32_t*>(&p1));
}

// ---------------- prep: transpose [R x Cc] fp32 -> [Cc x R] fp16 -------------
__global__ void transpose_cvt(const float* __restrict__ in,
                              fp16* __restrict__ outc, int R, int Cc) {
    __shared__ float t[32][33];
    const size_t mat = blockIdx.z;
    const float* src = in + mat * (size_t)R * Cc;
    fp16* dst = outc + mat * (size_t)Cc * R;
    int c0 = blockIdx.x * 32, r0 = blockIdx.y * 32;
    int tx = threadIdx.x;
    #pragma unroll
    for (int i = threadIdx.y; i < 32; i += 8)
        t[i][tx] = src[(size_t)(r0 + i) * Cc + c0 + tx];
    __syncthreads();
    #pragma unroll
    for (int i = threadIdx.y; i < 32; i += 8)
        dst[(size_t)(c0 + i) * R + r0 + tx] = __float2half(t[tx][i]);
}

// ---------------- launch ------------------------------------------------------
extern "C" void kernel_launch(void* const* d_in, const int* in_sizes, int n_in,
                              void* d_out, int out_size) {
    const float* x    = (const float*)d_in[0];   // [B,S,C]
    const int*   eidx = (const int*)d_in[1];     // [M,B]
    const float* dw   = (const float*)d_in[2];   // [M,N,C,D]
    const float* db   = (const float*)d_in[3];   // [M,N,D]
    const float* uw   = (const float*)d_in[4];   // [M,N,D,C]
    float*       out  = (float*)d_out;           // [M,B,S,C]

    fp16 *dwt, *uwt;
    cudaGetSymbolAddress((void**)&dwt, g_dwT);
    cudaGetSymbolAddress((void**)&uwt, g_uwT);

    cudaFuncSetAttribute(fused_mma, cudaFuncAttributeMaxDynamicSharedMemorySize, SMEM_TOTAL);

    // preps
    x_cvt<<<(BB * SS * CD / 4) / 256, 256>>>(x);
    transpose_cvt<<<dim3(DD / 32, CD / 32, MR * NE), dim3(32, 8)>>>(dw, dwt, CD, DD);
    transpose_cvt<<<dim3(CD / 32, DD / 32, MR * NE), dim3(32, 8)>>>(uw, uwt, DD, CD);

    // fused GEMM: one CTA per (stile, b, m)
    fused_mma<<<dim3(SS / 128, BB, MR), 512, SMEM_TOTAL>>>(eidx, db, out);
}

// round 10
// speedup vs baseline: 1.2982x; 1.2982x over previous
#include <cuda_runtime.h>
#include <cuda_fp16.h>
#include <math.h>
#include <stdint.h>

#define MR 2
#define NE 8
#define CD 1024
#define DD 256
#define BB 32
#define SS 512
#define STAGES 4
// stage: A 8KB ([128 m][32 k] fp16, row-swizzled) | B 8KB ([32 k][128 n] fp16, chunk-swizzled)
#define STAGE_BYTES 16384
#define OFF_B  8192
#define SMEM_TOTAL (STAGES * STAGE_BYTES)   // 65536; 2 CTAs/SM

typedef __half fp16;

// ---------------- static device scratch (no allocs) ----------------
__device__ fp16 g_x[(size_t)BB * SS * CD];        // x fp16 (C contiguous)
__device__ fp16 g_z[(size_t)MR * BB * SS * DD];   // z fp16 (D contiguous)
__device__ fp16 g_dw16[(size_t)MR * NE * CD * DD]; // dw fp16, NATIVE [C][D]
__device__ fp16 g_uw16[(size_t)MR * NE * DD * CD]; // uw fp16, NATIVE [D][C]

// ---------------- ptx helpers ----------------
__device__ __forceinline__ uint32_t smem_u32(const void* p) {
    uint32_t a;
    asm("{ .reg .u64 t; cvta.to.shared.u64 t, %1; cvt.u32.u64 %0, t; }" : "=r"(a) : "l"(p));
    return a;
}
#define CP16(dst, src) \
    asm volatile("cp.async.cg.shared.global [%0], [%1], 16;" :: "r"(dst), "l"(src))
#define CP_COMMIT() asm volatile("cp.async.commit_group;")
#define CP_WAIT2()  asm volatile("cp.async.wait_group 2;")
#define CP_WAIT1()  asm volatile("cp.async.wait_group 1;")
#define CP_WAIT0()  asm volatile("cp.async.wait_group 0;")

#define LDSM4(r, a) \
    asm volatile("ldmatrix.sync.aligned.m8n8.x4.shared.b16 {%0,%1,%2,%3}, [%4];" \
        : "=r"((r)[0]), "=r"((r)[1]), "=r"((r)[2]), "=r"((r)[3]) : "r"(a))
#define LDSM4T(r, a) \
    asm volatile("ldmatrix.sync.aligned.m8n8.x4.trans.shared.b16 {%0,%1,%2,%3}, [%4];" \
        : "=r"((r)[0]), "=r"((r)[1]), "=r"((r)[2]), "=r"((r)[3]) : "r"(a))

#define MMA(d, a, b0, b1) \
    asm volatile("mma.sync.aligned.m16n8k16.row.col.f32.f16.f16.f32 " \
        "{%0,%1,%2,%3},{%4,%5,%6,%7},{%8,%9},{%0,%1,%2,%3};" \
        : "+f"((d)[0]), "+f"((d)[1]), "+f"((d)[2]), "+f"((d)[3]) \
        : "r"((a)[0]), "r"((a)[1]), "r"((a)[2]), "r"((a)[3]), "r"(b0), "r"(b1))

// A-side swizzle: 64B rows (4 x 16B chunks)
__device__ __forceinline__ uint32_t swz(uint32_t row, uint32_t chunk) {
    return row * 64u + ((chunk ^ ((row >> 1) & 3u)) << 4);
}
// B-side (K-major) swizzle: 256B rows (16 x 16B chunks), chunk ^= row&7
__device__ __forceinline__ uint32_t bswz(uint32_t row, uint32_t chunk) {
    return row * 256u + ((chunk ^ (row & 7u)) << 4);
}

// ---------------- stage loader: 4x cp.async(16B) per thread ----------------
// A: [128 m][32 k] from A1 (row stride lda);  B: [32 k][128 n] from Bg row kc+r,
// col ncol0 + c*8 (row stride ldb)
__device__ __forceinline__ void stage_load(uint32_t sbase,
                                           const fp16* __restrict__ A1, int lda,
                                           const fp16* __restrict__ Bg, int ldb,
                                           int ncol0, int kc, int tid) {
    #pragma unroll
    for (int i = 0; i < 2; i++) {
        int q = tid + (i << 8);
        {   // A chunk: 512 = 128 rows x 4 chunks
            int r = q >> 2, c = q & 3;
            CP16(sbase + swz(r, c), A1 + (size_t)r * lda + kc + c * 8);
        }
        {   // B chunk: 512 = 32 rows x 16 chunks
            int r = q >> 4, c = q & 15;
            CP16(sbase + OFF_B + bswz(r, c),
                 Bg + (size_t)(kc + r) * ldb + ncol0 + c * 8);
        }
    }
}

// ---------------- GEMM mainloop: warp tile 64x32, acc[4][4][4] ----------------
__device__ __forceinline__ void gemm_main(uint32_t smem_b,
                                          const fp16* __restrict__ A1, int lda,
                                          const fp16* __restrict__ Bg, int ldb,
                                          int ncol0, int nk,
                                          float acc[4][4][4], int tid) {
    const int lane = tid & 31, warp = tid >> 5;
    const int wm = (warp & 1) * 64, wn = (warp >> 1) * 32;
    const int r15 = lane & 15, chi = lane >> 4;

    // A frag base (ks1 = chunk^2 = byte^32); rows+16 -> +1024
    const uint32_t a0 = swz((uint32_t)(wm + r15), (uint32_t)chi);
    // B frag bases for the two n16 blocks (j=0,1); ks1 = rows+16 -> +4096
    const uint32_t b0 = OFF_B + bswz((uint32_t)r15, (uint32_t)((wn >> 3) + chi));
    const uint32_t b1 = OFF_B + bswz((uint32_t)r15, (uint32_t)((wn >> 3) + 2 + chi));

    stage_load(smem_b,                   A1, lda, Bg, ldb, ncol0, 0,  tid);  CP_COMMIT();
    stage_load(smem_b + STAGE_BYTES,     A1, lda, Bg, ldb, ncol0, 32, tid);  CP_COMMIT();
    stage_load(smem_b + 2 * STAGE_BYTES, A1, lda, Bg, ldb, ncol0, 64, tid);  CP_COMMIT();

    uint32_t ah[4][4], bb[2][4];

    for (int k = 0; k < nk; k++) {
        if (k + 3 <= nk)      { CP_WAIT2(); }
        else if (k + 2 <= nk) { CP_WAIT1(); }
        else                  { CP_WAIT0(); }
        __syncthreads();
        if (k + 3 < nk) {
            stage_load(smem_b + ((k + 3) & 3) * STAGE_BYTES,
                       A1, lda, Bg, ldb, ncol0, (k + 3) * 32, tid);
            CP_COMMIT();
        }
        const uint32_t stg = smem_b + ((k & 3) << 14);

        #pragma unroll
        for (int ks = 0; ks < 2; ks++) {
            const uint32_t ax = stg + (ks ? (a0 ^ 32u) : a0);
            const uint32_t bof = ks ? 4096u : 0u;
            LDSM4T(bb[0], stg + b0 + bof);   // regs: {n0-7 k0-7, n0-7 k8-15, n8-15 k0-7, n8-15 k8-15}
            LDSM4T(bb[1], stg + b1 + bof);
            LDSM4(ah[0], ax);
            LDSM4(ah[1], ax + 1024);
            LDSM4(ah[2], ax + 2048);
            LDSM4(ah[3], ax + 3072);
            #pragma unroll
            for (int mt = 0; mt < 4; mt++)
                #pragma unroll
                for (int nt = 0; nt < 4; nt++)
                    MMA(acc[mt][nt], ah[mt],
                        bb[nt >> 1][2 * (nt & 1)], bb[nt >> 1][2 * (nt & 1) + 1]);
        }
    }
}

// ---------------- down: z = silu(x @ dw + db), fp16 z -------------------------
__global__ void __launch_bounds__(256, 2)
down_mma(const int* __restrict__ eidx, const float* __restrict__ db) {
    extern __shared__ char smem[];
    uint32_t smem_b = smem_u32(smem);
    const int tid = threadIdx.x, lane = tid & 31, warp = tid >> 5;
    const int wm = (warp & 1) * 64, wn = (warp >> 1) * 32;
    const int stile = blockIdx.x >> 1, ntile = blockIdx.x & 1;
    const int b = blockIdx.y, m = blockIdx.z;
    const int e = eidx[m * BB + b];

    const fp16* A1 = g_x    + ((size_t)b * SS + stile * 128) * CD;
    const fp16* Bg = g_dw16 + (size_t)(m * NE + e) * CD * DD;   // [C][D] K-major

    float acc[4][4][4];
    #pragma unroll
    for (int i = 0; i < 4; i++)
        #pragma unroll
        for (int j = 0; j < 4; j++)
            #pragma unroll
            for (int q = 0; q < 4; q++) acc[i][j][q] = 0.f;

    gemm_main(smem_b, A1, CD, Bg, DD, ntile * 128, CD / 32, acc, tid);

    const float* bias = db + (size_t)(m * NE + e) * DD;
    const size_t zrow0 = ((size_t)(m * BB + b) * SS + stile * 128);
    const int r0 = lane >> 2, cp = 2 * (lane & 3);

    #pragma unroll
    for (int mt = 0; mt < 4; mt++) {
        #pragma unroll
        for (int nt = 0; nt < 4; nt++) {
            const int col = ntile * 128 + wn + nt * 8 + cp;
            const float2 bv = *reinterpret_cast<const float2*>(bias + col);
            #pragma unroll
            for (int h = 0; h < 2; h++) {
                float v0 = acc[mt][nt][2 * h + 0] + bv.x;
                float v1 = acc[mt][nt][2 * h + 1] + bv.y;
                v0 = v0 / (1.f + __expf(-v0));
                v1 = v1 / (1.f + __expf(-v1));
                __half2 hp; hp.x = __float2half(v0); hp.y = __float2half(v1);
                *reinterpret_cast<__half2*>(
                    g_z + (zrow0 + wm + mt * 16 + r0 + h * 8) * DD + col) = hp;
            }
        }
    }
}

// ---------------- up: out = z @ uw (fp32 out) --------------------------------
__global__ void __launch_bounds__(256, 2)
up_mma(const int* __restrict__ eidx, float* __restrict__ out) {
    extern __shared__ char smem[];
    uint32_t smem_b = smem_u32(smem);
    const int tid = threadIdx.x, lane = tid & 31, warp = tid >> 5;
    const int wm = (warp & 1) * 64, wn = (warp >> 1) * 32;
    const int stile = blockIdx.x & 3, ctile = blockIdx.x >> 2;
    const int b = blockIdx.y, m = blockIdx.z;
    const int e = eidx[m * BB + b];

    const fp16* A1 = g_z    + ((size_t)(m * BB + b) * SS + stile * 128) * DD;
    const fp16* Bg = g_uw16 + (size_t)(m * NE + e) * DD * CD;   // [D][C] K-major

    float acc[4][4][4];
    #pragma unroll
    for (int i = 0; i < 4; i++)
        #pragma unroll
        for (int j = 0; j < 4; j++)
            #pragma unroll
            for (int q = 0; q < 4; q++) acc[i][j][q] = 0.f;

    gemm_main(smem_b, A1, DD, Bg, CD, ctile * 128, DD / 32, acc, tid);

    const size_t orow0 = ((size_t)(m * BB + b) * SS + stile * 128);
    const int r0 = lane >> 2, cp = 2 * (lane & 3);

    #pragma unroll
    for (int mt = 0; mt < 4; mt++) {
        #pragma unroll
        for (int nt = 0; nt < 4; nt++) {
            const int col = ctile * 128 + wn + nt * 8 + cp;
            #pragma unroll
            for (int h = 0; h < 2; h++) {
                const size_t off = (orow0 + wm + mt * 16 + r0 + h * 8) * CD + col;
                *reinterpret_cast<float2*>(out + off) =
                    make_float2(acc[mt][nt][2 * h + 0], acc[mt][nt][2 * h + 1]);
            }
        }
    }
}

// ---------------- prep: fused fp32 -> fp16 conversion of x, dw, uw ------------
#define NX4 ((size_t)BB * SS * CD / 4)        // 4,194,304 float4 groups
#define NW4 ((size_t)MR * NE * CD * DD / 4)   // 1,048,576 per weight tensor
__global__ void __launch_bounds__(256)
cvt_all(const float* __restrict__ x, const float* __restrict__ dw,
        const float* __restrict__ uw) {
    size_t g = (size_t)blockIdx.x * 256 + threadIdx.x;
    const float* src; fp16* dst; size_t i;
    if (g < NX4)            { src = x;  dst = g_x;    i = g; }
    else if (g < NX4 + NW4) { src = dw; dst = g_dw16; i = g - NX4; }
    else                    { src = uw; dst = g_uw16; i = g - NX4 - NW4; }
    float4 v = *reinterpret_cast<const float4*>(src + i * 4);
    __half2 p0, p1;
    p0.x = __float2half(v.x); p0.y = __float2half(v.y);
    p1.x = __float2half(v.z); p1.y = __float2half(v.w);
    *reinterpret_cast<uint2*>(dst + i * 4) =
        make_uint2(*reinterpret_cast<uint32_t*>(&p0), *reinterpret_cast<uint32_t*>(&p1));
}

// ---------------- launch ------------------------------------------------------
extern "C" void kernel_launch(void* const* d_in, const int* in_sizes, int n_in,
                              void* d_out, int out_size) {
    const float* x    = (const float*)d_in[0];   // [B,S,C]
    const int*   eidx = (const int*)d_in[1];     // [M,B]
    const float* dw   = (const float*)d_in[2];   // [M,N,C,D]
    const float* db   = (const float*)d_in[3];   // [M,N,D]
    const float* uw   = (const float*)d_in[4];   // [M,N,D,C]
    float*       out  = (float*)d_out;           // [M,B,S,C]

    cudaFuncSetAttribute(down_mma, cudaFuncAttributeMaxDynamicSharedMemorySize, SMEM_TOTAL);
    cudaFuncSetAttribute(up_mma,   cudaFuncAttributeMaxDynamicSharedMemorySize, SMEM_TOTAL);

    // single fused prep: coalesced fp32 -> fp16 for x, dw, uw (native layouts)
    cvt_all<<<(unsigned)((NX4 + 2 * NW4) / 256), 256>>>(x, dw, uw);

    // GEMMs (round-8 proven structure; B via ldmatrix.trans from K-major)
    down_mma<<<dim3(8, BB, MR), 256, SMEM_TOTAL>>>(eidx, db);
    up_mma<<<dim3(32, BB, MR), 256, SMEM_TOTAL>>>(eidx, out);
}